// round 3
// baseline (speedup 1.0000x reference)
#include <cuda_runtime.h>
#include <cuda_bf16.h>
#include <cstdint>

// Problem constants
#define BB 64
#define SS 2048
#define HH 512
#define KK 512

// Scratch (static __device__ — no allocation)
__device__ float g_c[BB * KK];           // e_fin + bias
__device__ float g_scores[BB * SS];      // scores, then softmax weights (in-place)
__device__ float g_part[BB * 8 * HH];    // context partial sums

// ---------------------------------------------------------------------------
// helpers
// ---------------------------------------------------------------------------
__device__ __forceinline__ uint32_t f2tf32(float x) {
    uint32_t r;
    asm("cvt.rna.tf32.f32 %0, %1;" : "=r"(r) : "f"(x));
    return r;
}

__device__ __forceinline__ void mma_tf32(float (&d)[4], const uint32_t (&a)[4],
                                         uint32_t b0, uint32_t b1) {
    asm volatile(
        "mma.sync.aligned.m16n8k8.row.col.f32.tf32.tf32.f32 "
        "{%0,%1,%2,%3},{%4,%5,%6,%7},{%8,%9},{%0,%1,%2,%3};"
        : "+f"(d[0]), "+f"(d[1]), "+f"(d[2]), "+f"(d[3])
        : "r"(a[0]), "r"(a[1]), "r"(a[2]), "r"(a[3]), "r"(b0), "r"(b1));
}

// ---------------------------------------------------------------------------
// Kernel A: c[b,k] = dot(fin[b,:], attn_w[k, 512:1024]) + attn_b[k]
// grid(64), block(256)
// ---------------------------------------------------------------------------
__global__ void cvec_kernel(const float* __restrict__ fin,
                            const float* __restrict__ attn_w,
                            const float* __restrict__ attn_b) {
    __shared__ float fsm[HH];
    int b = blockIdx.x;
    int t = threadIdx.x;
    fsm[t] = fin[b * HH + t];
    fsm[t + 256] = fin[b * HH + t + 256];
    __syncthreads();

    int warp = t >> 5, lane = t & 31;
    for (int k = warp; k < KK; k += 8) {
        const float* wp = attn_w + (size_t)k * (2 * HH) + HH;
        float s = 0.f;
        #pragma unroll 4
        for (int h = lane; h < HH; h += 32) s += fsm[h] * wp[h];
        #pragma unroll
        for (int o = 16; o > 0; o >>= 1) s += __shfl_xor_sync(0xffffffffu, s, o);
        if (lane == 0) g_c[b * KK + k] = s + attn_b[k];
    }
}

// ---------------------------------------------------------------------------
// Kernel B: fused scores = sum_k v[k]*tanh(enc @ w_enc^T + c)
// grid(16, 64): 128-row s-tile per block (blockIdx.x), batch b (blockIdx.y)
// block(256) = 8 warps arranged 4 (m) x 2 (n)
// TF32 mma m16n8k8; k-chunks of 128 looped inside the block.
// ---------------------------------------------------------------------------
__global__ __launch_bounds__(256) void scores_kernel(
    const float* __restrict__ enc,
    const float* __restrict__ attn_w,
    const float* __restrict__ vw) {
    __shared__ uint32_t As[128][36];   // enc tile  (tf32 bits), 128 s x 32 h
    __shared__ uint32_t Bs[128][36];   // w tile    (tf32 bits), 128 k x 32 h
    __shared__ float ssum[2][128];     // per-warp_n partial scores

    const int b = blockIdx.y;
    const int s0 = blockIdx.x * 128;
    const int tid = threadIdx.x;
    const int warp = tid >> 5, lane = tid & 31;
    const int g = lane >> 2, tg = lane & 3;
    const int warp_m = warp & 3;       // 0..3  -> 32-row slices
    const int warp_n = warp >> 2;      // 0..1  -> 64-col slices

    if (tid < 128) { ssum[0][tid] = 0.f; ssum[1][tid] = 0.f; }

    const float* cb = g_c + b * KK;

    // global load coordinates (shared by A and B tile loads)
    const int lrow = tid >> 3;           // 0..31
    const int lcol = (tid & 7) * 4;      // 0,4,...,28

    for (int kc = 0; kc < KK; kc += 128) {
        float acc[2][8][4];
        #pragma unroll
        for (int mi = 0; mi < 2; mi++)
            #pragma unroll
            for (int ni = 0; ni < 8; ni++)
                #pragma unroll
                for (int q = 0; q < 4; q++) acc[mi][ni][q] = 0.f;

        for (int h0 = 0; h0 < HH; h0 += 32) {
            __syncthreads();   // prior-iter readers done before overwrite
            const float* ap = enc + ((size_t)b * SS + s0 + lrow) * HH + h0 + lcol;
            const float* bp = attn_w + (size_t)(kc + lrow) * (2 * HH) + h0 + lcol;
            #pragma unroll
            for (int i = 0; i < 4; i++) {
                float4 av = *(const float4*)(ap + (size_t)i * 32 * HH);
                float4 bv = *(const float4*)(bp + (size_t)i * 32 * (2 * HH));
                int r = lrow + 32 * i;
                As[r][lcol + 0] = f2tf32(av.x);
                As[r][lcol + 1] = f2tf32(av.y);
                As[r][lcol + 2] = f2tf32(av.z);
                As[r][lcol + 3] = f2tf32(av.w);
                Bs[r][lcol + 0] = f2tf32(bv.x);
                Bs[r][lcol + 1] = f2tf32(bv.y);
                Bs[r][lcol + 2] = f2tf32(bv.z);
                Bs[r][lcol + 3] = f2tf32(bv.w);
            }
            __syncthreads();

            #pragma unroll
            for (int kk = 0; kk < 32; kk += 8) {
                uint32_t a[2][4];
                #pragma unroll
                for (int mi = 0; mi < 2; mi++) {
                    int m = warp_m * 32 + mi * 16;
                    a[mi][0] = As[m + g][kk + tg];
                    a[mi][1] = As[m + g + 8][kk + tg];
                    a[mi][2] = As[m + g][kk + tg + 4];
                    a[mi][3] = As[m + g + 8][kk + tg + 4];
                }
                #pragma unroll
                for (int ni = 0; ni < 8; ni++) {
                    int n = warp_n * 64 + ni * 8;
                    uint32_t b0 = Bs[n + g][kk + tg];
                    uint32_t b1 = Bs[n + g][kk + tg + 4];
                    mma_tf32(acc[0][ni], a[0], b0, b1);
                    mma_tf32(acc[1][ni], a[1], b0, b1);
                }
            }
        }

        // epilogue: tanh(acc + c) * v, reduce over this 128-k chunk
        float rs[4] = {0.f, 0.f, 0.f, 0.f};
        #pragma unroll
        for (int ni = 0; ni < 8; ni++) {
            int kg = kc + warp_n * 64 + ni * 8 + tg * 2;
            float c0 = cb[kg], c1 = cb[kg + 1];
            float v0 = vw[kg], v1 = vw[kg + 1];
            #pragma unroll
            for (int mi = 0; mi < 2; mi++) {
                rs[mi * 2 + 0] += tanhf(acc[mi][ni][0] + c0) * v0
                                + tanhf(acc[mi][ni][1] + c1) * v1;
                rs[mi * 2 + 1] += tanhf(acc[mi][ni][2] + c0) * v0
                                + tanhf(acc[mi][ni][3] + c1) * v1;
            }
        }
        #pragma unroll
        for (int i = 0; i < 4; i++) {
            rs[i] += __shfl_xor_sync(0xffffffffu, rs[i], 1);
            rs[i] += __shfl_xor_sync(0xffffffffu, rs[i], 2);
        }
        if (tg == 0) {
            int r = warp_m * 32 + g;   // rows r, r+8, r+16, r+24; unique owner lane
            ssum[warp_n][r]      += rs[0];
            ssum[warp_n][r + 8]  += rs[1];
            ssum[warp_n][r + 16] += rs[2];
            ssum[warp_n][r + 24] += rs[3];
        }
    }
    __syncthreads();
    if (tid < 128)
        g_scores[b * SS + s0 + tid] = ssum[0][tid] + ssum[1][tid];
}

// ---------------------------------------------------------------------------
// Kernel C: softmax over s (2048) per batch; in-place on g_scores
// grid(64), block(256)
// ---------------------------------------------------------------------------
__global__ void softmax_kernel() {
    __shared__ float red[256];
    int b = blockIdx.x, t = threadIdx.x;
    float v[8];
    float m = -1e30f;
    #pragma unroll
    for (int i = 0; i < 8; i++) {
        v[i] = g_scores[b * SS + i * 256 + t];
        m = fmaxf(m, v[i]);
    }
    red[t] = m;
    __syncthreads();
    for (int o = 128; o > 0; o >>= 1) {
        if (t < o) red[t] = fmaxf(red[t], red[t + o]);
        __syncthreads();
    }
    float mx = red[0];
    __syncthreads();
    float s = 0.f;
    #pragma unroll
    for (int i = 0; i < 8; i++) {
        v[i] = __expf(v[i] - mx);
        s += v[i];
    }
    red[t] = s;
    __syncthreads();
    for (int o = 128; o > 0; o >>= 1) {
        if (t < o) red[t] += red[t + o];
        __syncthreads();
    }
    float inv = 1.f / red[0];
    #pragma unroll
    for (int i = 0; i < 8; i++)
        g_scores[b * SS + i * 256 + t] = v[i] * inv;
}

// ---------------------------------------------------------------------------
// Kernel D: context partials: part[b,sc,h] = sum over 256 s of w*enc
// grid(8, 64), block(512)
// ---------------------------------------------------------------------------
__global__ void context_kernel(const float* __restrict__ enc) {
    __shared__ float ws[256];
    int b = blockIdx.y, sc = blockIdx.x;
    int h = threadIdx.x;
    if (h < 256) ws[h] = g_scores[b * SS + sc * 256 + h];
    __syncthreads();
    const float* ep = enc + ((size_t)b * SS + sc * 256) * HH + h;
    float a0 = 0.f, a1 = 0.f, a2 = 0.f, a3 = 0.f;
    #pragma unroll 2
    for (int j = 0; j < 256; j += 4) {
        a0 += ws[j + 0] * ep[(size_t)(j + 0) * HH];
        a1 += ws[j + 1] * ep[(size_t)(j + 1) * HH];
        a2 += ws[j + 2] * ep[(size_t)(j + 2) * HH];
        a3 += ws[j + 3] * ep[(size_t)(j + 3) * HH];
    }
    g_part[((b << 3) + sc) * HH + h] = (a0 + a1) + (a2 + a3);
}

// ---------------------------------------------------------------------------
// Kernel E: reduce 8 partials -> context
// grid(64), block(512)
// ---------------------------------------------------------------------------
__global__ void reduce_ctx(float* __restrict__ out) {
    int b = blockIdx.x, h = threadIdx.x;
    float s = 0.f;
    #pragma unroll
    for (int i = 0; i < 8; i++) s += g_part[((b << 3) + i) * HH + h];
    out[b * HH + h] = s;
}

// ---------------------------------------------------------------------------
extern "C" void kernel_launch(void* const* d_in, const int* in_sizes, int n_in,
                              void* d_out, int out_size) {
    const float* enc    = (const float*)d_in[0];   // (64, 2048, 512)
    const float* fin    = (const float*)d_in[1];   // (64, 512)
    const float* attn_w = (const float*)d_in[2];   // (512, 1024)
    const float* attn_b = (const float*)d_in[3];   // (512,)
    const float* v_w    = (const float*)d_in[4];   // (1, 512)
    float* out = (float*)d_out;                    // (64, 512)

    cvec_kernel<<<BB, 256>>>(fin, attn_w, attn_b);
    scores_kernel<<<dim3(SS / 128, BB), 256>>>(enc, attn_w, v_w);
    softmax_kernel<<<BB, 256>>>();
    context_kernel<<<dim3(8, BB), 512>>>(enc);
    reduce_ctx<<<BB, 512>>>(out);
}

// round 4
// speedup vs baseline: 1.3809x; 1.3809x over previous
#include <cuda_runtime.h>
#include <cuda_bf16.h>
#include <cstdint>

// Problem constants
#define BB 64
#define SS 2048
#define HH 512
#define KK 512

// Scratch (static __device__ — no allocation)
__device__ float g_c[BB * KK];            // e_fin + bias
__device__ float g_scores[BB * SS];       // scores, then softmax weights (in-place)
__device__ float g_part[BB * 16 * HH];    // context partial sums

// ---------------------------------------------------------------------------
// helpers
// ---------------------------------------------------------------------------
__device__ __forceinline__ void mma_tf32(float (&d)[4], const uint32_t (&a)[4],
                                         uint32_t b0, uint32_t b1) {
    asm volatile(
        "mma.sync.aligned.m16n8k8.row.col.f32.tf32.tf32.f32 "
        "{%0,%1,%2,%3},{%4,%5,%6,%7},{%8,%9},{%0,%1,%2,%3};"
        : "+f"(d[0]), "+f"(d[1]), "+f"(d[2]), "+f"(d[3])
        : "r"(a[0]), "r"(a[1]), "r"(a[2]), "r"(a[3]), "r"(b0), "r"(b1));
}

__device__ __forceinline__ float tanha(float x) {
    float y;
    asm("tanh.approx.f32 %0, %1;" : "=f"(y) : "f"(x));
    return y;
}

__device__ __forceinline__ void cp16(uint32_t dst, const void* src) {
    asm volatile("cp.async.cg.shared.global [%0], [%1], 16;" :: "r"(dst), "l"(src));
}
__device__ __forceinline__ void cp_commit() {
    asm volatile("cp.async.commit_group;");
}

// ---------------------------------------------------------------------------
// Kernel A: c[b,k] = dot(fin[b,:], attn_w[k, 512:1024]) + attn_b[k]
// ---------------------------------------------------------------------------
__global__ void cvec_kernel(const float* __restrict__ fin,
                            const float* __restrict__ attn_w,
                            const float* __restrict__ attn_b) {
    __shared__ float fsm[HH];
    int b = blockIdx.x;
    int t = threadIdx.x;
    fsm[t] = fin[b * HH + t];
    fsm[t + 256] = fin[b * HH + t + 256];
    __syncthreads();

    int warp = t >> 5, lane = t & 31;
    for (int k = warp; k < KK; k += 8) {
        const float* wp = attn_w + (size_t)k * (2 * HH) + HH;
        float s = 0.f;
        #pragma unroll 4
        for (int h = lane; h < HH; h += 32) s += fsm[h] * wp[h];
        #pragma unroll
        for (int o = 16; o > 0; o >>= 1) s += __shfl_xor_sync(0xffffffffu, s, o);
        if (lane == 0) g_c[b * KK + k] = s + attn_b[k];
    }
}

// ---------------------------------------------------------------------------
// Kernel B: fused scores = sum_k v[k]*tanh(enc @ w_enc^T + c)
// grid(16, 64): 128-row s-tile (x), batch (y). Block 256 = 8 warps, 2m x 4n,
// warp tile 64m x 64k. Block tile 128s x 256k, 2 kc iterations.
// cp.async double-buffered smem pipeline, raw-fp32-bits TF32 mma.
//
// Dynamic smem layout (uint32 words):
//   As[2][128*36]  @ 0        (4608 per buf)
//   Bs[2][256*36]  @ 9216     (9216 per buf)
//   ssum[4][128]   @ 27648    (float)
// total 28160 words = 112640 bytes
// ---------------------------------------------------------------------------
#define SPAD 36
#define AS_WORDS (128 * SPAD)
#define BS_WORDS (256 * SPAD)
#define SS_OFF (2 * AS_WORDS + 2 * BS_WORDS)
#define SMEM_BYTES ((SS_OFF + 4 * 128) * 4)

extern __shared__ uint32_t sdyn[];

__global__ __launch_bounds__(256, 1) void scores_kernel(
    const float* __restrict__ enc,
    const float* __restrict__ attn_w,
    const float* __restrict__ vw) {

    const int b = blockIdx.y;
    const int s0 = blockIdx.x * 128;
    const int tid = threadIdx.x;
    const int warp = tid >> 5, lane = tid & 31;
    const int g = lane >> 2, tg = lane & 3;
    const int warp_m = warp >> 2;      // 0..1 -> 64-row slices
    const int warp_n = warp & 3;       // 0..3 -> 64-col (k) slices

    float* ssum = (float*)(sdyn + SS_OFF);
    if (tid < 128) {
        ssum[tid] = 0.f; ssum[128 + tid] = 0.f;
        ssum[256 + tid] = 0.f; ssum[384 + tid] = 0.f;
    }

    const uint32_t sbase = (uint32_t)__cvta_generic_to_shared(sdyn);
    const float* cb = g_c + b * KK;

    // prefetch lambda-ish: chunk c -> kc=(c>>4)*256, h0=(c&15)*32, buf=c&1
    auto prefetch = [&](int c) {
        const int buf = c & 1;
        const int kc = (c >> 4) << 8;
        const int h0 = (c & 15) << 5;
        const uint32_t abase = sbase + (buf * AS_WORDS) * 4;
        const uint32_t bbase = sbase + (2 * AS_WORDS + buf * BS_WORDS) * 4;
        #pragma unroll
        for (int i = 0; i < 4; i++) {            // A: 128 rows x 32 h
            int idx = tid + i * 256;
            int row = idx >> 3, col = (idx & 7) * 4;
            cp16(abase + (row * SPAD + col) * 4,
                 enc + ((size_t)b * SS + s0 + row) * HH + h0 + col);
        }
        #pragma unroll
        for (int i = 0; i < 8; i++) {            // B: 256 rows x 32 h
            int idx = tid + i * 256;
            int row = idx >> 3, col = (idx & 7) * 4;
            cp16(bbase + (row * SPAD + col) * 4,
                 attn_w + (size_t)(kc + row) * (2 * HH) + h0 + col);
        }
        cp_commit();
    };

    float acc[4][8][4];
    #pragma unroll
    for (int mi = 0; mi < 4; mi++)
        #pragma unroll
        for (int ni = 0; ni < 8; ni++)
            #pragma unroll
            for (int q = 0; q < 4; q++) acc[mi][ni][q] = 0.f;

    prefetch(0);

    #pragma unroll 1
    for (int c = 0; c < 32; c++) {
        if (c + 1 < 32) prefetch(c + 1);
        if (c + 1 < 32) asm volatile("cp.async.wait_group 1;");
        else            asm volatile("cp.async.wait_group 0;");
        __syncthreads();

        const int buf = c & 1;
        const uint32_t* As_ = sdyn + buf * AS_WORDS;
        const uint32_t* Bs_ = sdyn + 2 * AS_WORDS + buf * BS_WORDS;

        #pragma unroll
        for (int kk = 0; kk < 32; kk += 8) {
            uint32_t a[4][4];
            #pragma unroll
            for (int mi = 0; mi < 4; mi++) {
                int m = warp_m * 64 + mi * 16;
                a[mi][0] = As_[(m + g) * SPAD + kk + tg];
                a[mi][1] = As_[(m + g + 8) * SPAD + kk + tg];
                a[mi][2] = As_[(m + g) * SPAD + kk + tg + 4];
                a[mi][3] = As_[(m + g + 8) * SPAD + kk + tg + 4];
            }
            #pragma unroll
            for (int ni = 0; ni < 8; ni++) {
                int n = warp_n * 64 + ni * 8;
                uint32_t b0 = Bs_[(n + g) * SPAD + kk + tg];
                uint32_t b1 = Bs_[(n + g) * SPAD + kk + tg + 4];
                mma_tf32(acc[0][ni], a[0], b0, b1);
                mma_tf32(acc[1][ni], a[1], b0, b1);
                mma_tf32(acc[2][ni], a[2], b0, b1);
                mma_tf32(acc[3][ni], a[3], b0, b1);
            }
        }

        if ((c & 15) == 15) {
            // epilogue for this kc: tanh(acc + c)*v, reduce over 64 k per warp
            const int kc = (c >> 4) << 8;
            float rs[8];
            #pragma unroll
            for (int i = 0; i < 8; i++) rs[i] = 0.f;
            #pragma unroll
            for (int ni = 0; ni < 8; ni++) {
                int kg = kc + warp_n * 64 + ni * 8 + tg * 2;
                float c0 = cb[kg], c1 = cb[kg + 1];
                float v0 = vw[kg], v1 = vw[kg + 1];
                #pragma unroll
                for (int mi = 0; mi < 4; mi++) {
                    rs[mi * 2 + 0] += tanha(acc[mi][ni][0] + c0) * v0
                                    + tanha(acc[mi][ni][1] + c1) * v1;
                    rs[mi * 2 + 1] += tanha(acc[mi][ni][2] + c0) * v0
                                    + tanha(acc[mi][ni][3] + c1) * v1;
                    acc[mi][ni][0] = 0.f; acc[mi][ni][1] = 0.f;
                    acc[mi][ni][2] = 0.f; acc[mi][ni][3] = 0.f;
                }
            }
            #pragma unroll
            for (int i = 0; i < 8; i++) {
                rs[i] += __shfl_xor_sync(0xffffffffu, rs[i], 1);
                rs[i] += __shfl_xor_sync(0xffffffffu, rs[i], 2);
            }
            if (tg == 0) {
                #pragma unroll
                for (int mi = 0; mi < 4; mi++) {
                    int row = warp_m * 64 + mi * 16 + g;
                    ssum[warp_n * 128 + row]     += rs[mi * 2 + 0];
                    ssum[warp_n * 128 + row + 8] += rs[mi * 2 + 1];
                }
            }
        }
        __syncthreads();
    }

    if (tid < 128)
        g_scores[b * SS + s0 + tid] =
            (ssum[tid] + ssum[128 + tid]) + (ssum[256 + tid] + ssum[384 + tid]);
}

// ---------------------------------------------------------------------------
// Kernel C: softmax over s (2048) per batch; in-place on g_scores
// ---------------------------------------------------------------------------
__global__ void softmax_kernel() {
    __shared__ float red[256];
    int b = blockIdx.x, t = threadIdx.x;
    float v[8];
    float m = -1e30f;
    #pragma unroll
    for (int i = 0; i < 8; i++) {
        v[i] = g_scores[b * SS + i * 256 + t];
        m = fmaxf(m, v[i]);
    }
    red[t] = m;
    __syncthreads();
    for (int o = 128; o > 0; o >>= 1) {
        if (t < o) red[t] = fmaxf(red[t], red[t + o]);
        __syncthreads();
    }
    float mx = red[0];
    __syncthreads();
    float s = 0.f;
    #pragma unroll
    for (int i = 0; i < 8; i++) {
        v[i] = __expf(v[i] - mx);
        s += v[i];
    }
    red[t] = s;
    __syncthreads();
    for (int o = 128; o > 0; o >>= 1) {
        if (t < o) red[t] += red[t + o];
        __syncthreads();
    }
    float inv = 1.f / red[0];
    #pragma unroll
    for (int i = 0; i < 8; i++)
        g_scores[b * SS + i * 256 + t] = v[i] * inv;
}

// ---------------------------------------------------------------------------
// Kernel D: context partials over 128-s chunks, float4 per thread
// grid(16, 64), block(128)
// ---------------------------------------------------------------------------
__global__ void context_kernel(const float* __restrict__ enc) {
    __shared__ float ws[128];
    int b = blockIdx.y, sc = blockIdx.x;
    int t = threadIdx.x;
    ws[t] = g_scores[b * SS + sc * 128 + t];
    __syncthreads();
    const float4* ep =
        (const float4*)(enc + ((size_t)b * SS + sc * 128) * HH) + t;
    float ax = 0.f, ay = 0.f, az = 0.f, aw = 0.f;
    #pragma unroll 8
    for (int j = 0; j < 128; j++) {
        float w = ws[j];
        float4 e = ep[(size_t)j * 128];
        ax += w * e.x; ay += w * e.y; az += w * e.z; aw += w * e.w;
    }
    float4 r; r.x = ax; r.y = ay; r.z = az; r.w = aw;
    ((float4*)(g_part + ((size_t)(b * 16 + sc)) * HH))[t] = r;
}

// ---------------------------------------------------------------------------
// Kernel E: reduce 16 partials -> context
// ---------------------------------------------------------------------------
__global__ void reduce_ctx(float* __restrict__ out) {
    int b = blockIdx.x, h = threadIdx.x;
    float s = 0.f;
    #pragma unroll
    for (int i = 0; i < 16; i++) s += g_part[((size_t)(b * 16 + i)) * HH + h];
    out[b * HH + h] = s;
}

// ---------------------------------------------------------------------------
extern "C" void kernel_launch(void* const* d_in, const int* in_sizes, int n_in,
                              void* d_out, int out_size) {
    const float* enc    = (const float*)d_in[0];   // (64, 2048, 512)
    const float* fin    = (const float*)d_in[1];   // (64, 512)
    const float* attn_w = (const float*)d_in[2];   // (512, 1024)
    const float* attn_b = (const float*)d_in[3];   // (512,)
    const float* v_w    = (const float*)d_in[4];   // (1, 512)
    float* out = (float*)d_out;                    // (64, 512)

    cudaFuncSetAttribute(scores_kernel,
                         cudaFuncAttributeMaxDynamicSharedMemorySize, SMEM_BYTES);

    cvec_kernel<<<BB, 256>>>(fin, attn_w, attn_b);
    scores_kernel<<<dim3(SS / 128, BB), 256, SMEM_BYTES>>>(enc, attn_w, v_w);
    softmax_kernel<<<BB, 256>>>();
    context_kernel<<<dim3(16, BB), 128>>>(enc);
    reduce_ctx<<<BB, 512>>>(out);
}

// round 6
// speedup vs baseline: 1.9410x; 1.4056x over previous
#include <cuda_runtime.h>
#include <cuda_fp16.h>
#include <cstdint>

// Problem constants
#define BB 64
#define SS 2048
#define HH 512
#define KK 512

// Scratch (static __device__ — no allocation)
__device__ float  g_c[BB * KK];            // e_fin + bias
__device__ float  g_scores[BB * SS];       // scores, then softmax weights
__device__ float  g_part[BB * 16 * HH];    // context partial sums
__device__ __half g_ench[(size_t)BB * SS * HH];   // enc in fp16 (128 MiB)
__device__ __half g_wh[KK * HH];                  // w_enc in fp16

// ---------------------------------------------------------------------------
// helpers
// ---------------------------------------------------------------------------
__device__ __forceinline__ float tanha(float x) {
    float y;
    asm("tanh.approx.f32 %0, %1;" : "=f"(y) : "f"(x));
    return y;
}
__device__ __forceinline__ void cp16(uint32_t dst, const void* src) {
    asm volatile("cp.async.cg.shared.global [%0], [%1], 16;" :: "r"(dst), "l"(src));
}
__device__ __forceinline__ void cp_commit() {
    asm volatile("cp.async.commit_group;");
}
__device__ __forceinline__ void ldsm4(uint32_t (&r)[4], uint32_t addr) {
    asm volatile("ldmatrix.sync.aligned.m8n8.x4.shared.b16 {%0,%1,%2,%3}, [%4];"
                 : "=r"(r[0]), "=r"(r[1]), "=r"(r[2]), "=r"(r[3]) : "r"(addr));
}
__device__ __forceinline__ void mma_f16(float (&d)[4], const uint32_t (&a)[4],
                                        uint32_t b0, uint32_t b1) {
    asm volatile(
        "mma.sync.aligned.m16n8k16.row.col.f32.f16.f16.f32 "
        "{%0,%1,%2,%3},{%4,%5,%6,%7},{%8,%9},{%0,%1,%2,%3};"
        : "+f"(d[0]), "+f"(d[1]), "+f"(d[2]), "+f"(d[3])
        : "r"(a[0]), "r"(a[1]), "r"(a[2]), "r"(a[3]), "r"(b0), "r"(b1));
}

// ---------------------------------------------------------------------------
// Conversion kernels: fp32 -> fp16 (RN)
// ---------------------------------------------------------------------------
__global__ void conv_enc_kernel(const float* __restrict__ enc) {
    size_t idx = (size_t)blockIdx.x * 256 + threadIdx.x;   // float4 index
    float4 v = ((const float4*)enc)[idx];
    __half2* o = (__half2*)g_ench + idx * 2;
    o[0] = __floats2half2_rn(v.x, v.y);
    o[1] = __floats2half2_rn(v.z, v.w);
}

__global__ void conv_w_kernel(const float* __restrict__ attn_w) {
    int k = blockIdx.x, t = threadIdx.x;
    float2 v = *(const float2*)(attn_w + (size_t)k * (2 * HH) + 2 * t);
    ((__half2*)g_wh)[k * (HH / 2) + t] = __floats2half2_rn(v.x, v.y);
}

// ---------------------------------------------------------------------------
// Kernel A: c[b,k] = dot(fin[b,:], attn_w[k, 512:1024]) + attn_b[k]  (fp32)
// ---------------------------------------------------------------------------
__global__ void cvec_kernel(const float* __restrict__ fin,
                            const float* __restrict__ attn_w,
                            const float* __restrict__ attn_b) {
    __shared__ float fsm[HH];
    int b = blockIdx.x;
    int t = threadIdx.x;
    fsm[t] = fin[b * HH + t];
    fsm[t + 256] = fin[b * HH + t + 256];
    __syncthreads();

    int warp = t >> 5, lane = t & 31;
    for (int k = warp; k < KK; k += 8) {
        const float* wp = attn_w + (size_t)k * (2 * HH) + HH;
        float s = 0.f;
        #pragma unroll 4
        for (int h = lane; h < HH; h += 32) s += fsm[h] * wp[h];
        #pragma unroll
        for (int o = 16; o > 0; o >>= 1) s += __shfl_xor_sync(0xffffffffu, s, o);
        if (lane == 0) g_c[b * KK + k] = s + attn_b[k];
    }
}

// ---------------------------------------------------------------------------
// Kernel B: fused scores = sum_k v[k]*tanh(enc @ w_enc^T + c), fp16 mma.
// grid(16, 64): 128-s tile (x), batch (y). 256 thr = 8 warps (2 warp_m x 4
// warp_n), warp tile 64m x 64k_out. Block n-tile 256, 2 kc passes.
// A (enc) persistent in smem 128x512 fp16; B (w) double-buffered, 64-h chunks.
//
// SMEM (bytes): cs[512]f32 @0, vs[512]f32 @2048, ssum[4][128]f32 @4096,
//               A @8192 (128 rows x 1024B, XOR16 swizzle),
//               B @139264 (2 bufs x 256 rows x 128B, XOR16 swizzle)
// ---------------------------------------------------------------------------
#define SM_CS   0
#define SM_VS   2048
#define SM_SSUM 4096
#define SM_A    8192
#define SM_B    139264
#define BBUF    32768
#define SMEM_BYTES 204800

extern __shared__ uint32_t sdyn[];

__global__ __launch_bounds__(256, 1) void scores_fp16(const float* __restrict__ vw) {
    const int b = blockIdx.y;
    const int s0 = blockIdx.x * 128;
    const int tid = threadIdx.x;
    const int warp = tid >> 5, lane = tid & 31;
    const int g = lane >> 2, tg = lane & 3;
    const int warp_m = warp >> 2;      // 0..1
    const int warp_n = warp & 3;       // 0..3
    const uint32_t sbase = (uint32_t)__cvta_generic_to_shared(sdyn);

    float* cs = (float*)((char*)sdyn + SM_CS);
    float* vs = (float*)((char*)sdyn + SM_VS);
    float* ssum = (float*)((char*)sdyn + SM_SSUM);

    cs[tid] = g_c[b * KK + tid];
    cs[tid + 256] = g_c[b * KK + tid + 256];
    vs[tid] = vw[tid];
    vs[tid + 256] = vw[tid + 256];
    ssum[tid] = 0.f;
    ssum[tid + 256] = 0.f;

    // ---- A tile: 128 rows x 512 halves (1024 B/row), cp.async ----
    {
        const __half* src0 = g_ench + ((size_t)b * SS + s0) * HH;
        #pragma unroll
        for (int i = 0; i < 32; i++) {
            int idx = tid + i * 256;
            int row = idx >> 6, c16 = idx & 63;
            uint32_t dst = sbase + SM_A + row * 1024 + ((c16 * 16) ^ ((row & 7) << 4));
            cp16(dst, src0 + (size_t)row * HH + c16 * 8);
        }
        cp_commit();
    }

    // ---- B chunk loader: chunk c -> kc=(c>>3)*256, h0=(c&7)*64 halves ----
    auto loadB = [&](int c) {
        const uint32_t bb = sbase + SM_B + (c & 1) * BBUF;
        const int kc = (c >> 3) << 8;
        const int h0 = (c & 7) << 6;
        #pragma unroll
        for (int i = 0; i < 8; i++) {
            int idx = tid + i * 256;
            int row = idx >> 3, c16 = idx & 7;
            uint32_t dst = bb + row * 128 + ((c16 * 16) ^ ((row & 7) << 4));
            cp16(dst, g_wh + (size_t)(kc + row) * HH + h0 + c16 * 8);
        }
        cp_commit();
    };
    loadB(0);

    // ---- lane-constant ldmatrix addressing ----
    const int arow = warp_m * 64 + (lane & 7) + ((lane >> 3) & 1) * 8;   // +mi*16
    const int brow = warp_n * 64 + (lane & 7) + ((lane >> 3) & 1) * 8;   // +nip*16
    const int lcol16 = ((lane >> 4) & 1) * 16;    // +16B for k+8 matrices
    const uint32_t a_lane = sbase + SM_A + arow * 1024;
    const uint32_t xor_a = (arow & 7) << 4;
    const uint32_t xor_b = (brow & 7) << 4;

    float acc[4][8][4];
    #pragma unroll
    for (int mi = 0; mi < 4; mi++)
        #pragma unroll
        for (int ni = 0; ni < 8; ni++)
            #pragma unroll
            for (int q = 0; q < 4; q++) acc[mi][ni][q] = 0.f;

    #pragma unroll 1
    for (int c = 0; c < 16; c++) {
        if (c < 15) {
            loadB(c + 1);
            asm volatile("cp.async.wait_group 1;");
        } else {
            asm volatile("cp.async.wait_group 0;");
        }
        __syncthreads();

        const uint32_t bb = sbase + SM_B + (c & 1) * BBUF + brow * 128;
        const int hbase = (c & 7) * 128;   // byte offset of chunk within A row

        #pragma unroll
        for (int kk = 0; kk < 4; kk++) {
            const uint32_t hoff = (uint32_t)(hbase + kk * 32 + lcol16);
            uint32_t a[4][4];
            #pragma unroll
            for (int mi = 0; mi < 4; mi++)
                ldsm4(a[mi], a_lane + mi * 16384 + (hoff ^ xor_a));
            #pragma unroll
            for (int nip = 0; nip < 4; nip++) {
                uint32_t r[4];
                ldsm4(r, bb + nip * 2048 + (((uint32_t)(kk * 32 + lcol16)) ^ xor_b));
                #pragma unroll
                for (int mi = 0; mi < 4; mi++) {
                    mma_f16(acc[mi][2 * nip], a[mi], r[0], r[2]);
                    mma_f16(acc[mi][2 * nip + 1], a[mi], r[1], r[3]);
                }
            }
        }

        if ((c & 7) == 7) {
            // epilogue for this kc: tanh(acc + c)*v, reduce 64 k per warp
            const int kc = (c >> 3) << 8;
            float rs[8];
            #pragma unroll
            for (int i = 0; i < 8; i++) rs[i] = 0.f;
            #pragma unroll
            for (int ni = 0; ni < 8; ni++) {
                int kg = kc + warp_n * 64 + ni * 8 + tg * 2;
                float c0 = cs[kg], c1 = cs[kg + 1];
                float v0 = vs[kg], v1 = vs[kg + 1];
                #pragma unroll
                for (int mi = 0; mi < 4; mi++) {
                    rs[mi * 2 + 0] += tanha(acc[mi][ni][0] + c0) * v0
                                    + tanha(acc[mi][ni][1] + c1) * v1;
                    rs[mi * 2 + 1] += tanha(acc[mi][ni][2] + c0) * v0
                                    + tanha(acc[mi][ni][3] + c1) * v1;
                    acc[mi][ni][0] = 0.f; acc[mi][ni][1] = 0.f;
                    acc[mi][ni][2] = 0.f; acc[mi][ni][3] = 0.f;
                }
            }
            #pragma unroll
            for (int i = 0; i < 8; i++) {
                rs[i] += __shfl_xor_sync(0xffffffffu, rs[i], 1);
                rs[i] += __shfl_xor_sync(0xffffffffu, rs[i], 2);
            }
            if (tg == 0) {
                #pragma unroll
                for (int mi = 0; mi < 4; mi++) {
                    int row = warp_m * 64 + mi * 16 + g;
                    ssum[warp_n * 128 + row]     += rs[mi * 2 + 0];
                    ssum[warp_n * 128 + row + 8] += rs[mi * 2 + 1];
                }
            }
        }
        __syncthreads();
    }

    if (tid < 128)
        g_scores[b * SS + s0 + tid] =
            (ssum[tid] + ssum[128 + tid]) + (ssum[256 + tid] + ssum[384 + tid]);
}

// ---------------------------------------------------------------------------
// Kernel C: softmax over s (2048) per batch; in-place on g_scores
// ---------------------------------------------------------------------------
__global__ void softmax_kernel() {
    __shared__ float red[256];
    int b = blockIdx.x, t = threadIdx.x;
    float v[8];
    float m = -1e30f;
    #pragma unroll
    for (int i = 0; i < 8; i++) {
        v[i] = g_scores[b * SS + i * 256 + t];
        m = fmaxf(m, v[i]);
    }
    red[t] = m;
    __syncthreads();
    for (int o = 128; o > 0; o >>= 1) {
        if (t < o) red[t] = fmaxf(red[t], red[t + o]);
        __syncthreads();
    }
    float mx = red[0];
    __syncthreads();
    float s = 0.f;
    #pragma unroll
    for (int i = 0; i < 8; i++) {
        v[i] = __expf(v[i] - mx);
        s += v[i];
    }
    red[t] = s;
    __syncthreads();
    for (int o = 128; o > 0; o >>= 1) {
        if (t < o) red[t] += red[t + o];
        __syncthreads();
    }
    float inv = 1.f / red[0];
    #pragma unroll
    for (int i = 0; i < 8; i++)
        g_scores[b * SS + i * 256 + t] = v[i] * inv;
}

// ---------------------------------------------------------------------------
// Kernel D: context partials over 128-s chunks, fp16 enc (halved traffic)
// grid(16, 64), block(128); thread t owns h = 4t..4t+3
// ---------------------------------------------------------------------------
__global__ void context_kernel() {
    __shared__ float ws[128];
    int b = blockIdx.y, sc = blockIdx.x;
    int t = threadIdx.x;
    ws[t] = g_scores[b * SS + sc * 128 + t];
    __syncthreads();
    const __half* ep = g_ench + ((size_t)b * SS + sc * 128) * HH + 4 * t;
    float ax = 0.f, ay = 0.f, az = 0.f, aw = 0.f;
    #pragma unroll 4
    for (int j = 0; j < 128; j++) {
        float w = ws[j];
        uint2 u = *(const uint2*)(ep + (size_t)j * HH);
        float2 f0 = __half22float2(*reinterpret_cast<const __half2*>(&u.x));
        float2 f1 = __half22float2(*reinterpret_cast<const __half2*>(&u.y));
        ax += w * f0.x; ay += w * f0.y; az += w * f1.x; aw += w * f1.y;
    }
    float4 r; r.x = ax; r.y = ay; r.z = az; r.w = aw;
    ((float4*)(g_part + ((size_t)(b * 16 + sc)) * HH))[t] = r;
}

// ---------------------------------------------------------------------------
// Kernel E: reduce 16 partials -> context
// ---------------------------------------------------------------------------
__global__ void reduce_ctx(float* __restrict__ out) {
    int b = blockIdx.x, h = threadIdx.x;
    float s = 0.f;
    #pragma unroll
    for (int i = 0; i < 16; i++) s += g_part[((size_t)(b * 16 + i)) * HH + h];
    out[b * HH + h] = s;
}

// ---------------------------------------------------------------------------
extern "C" void kernel_launch(void* const* d_in, const int* in_sizes, int n_in,
                              void* d_out, int out_size) {
    const float* enc    = (const float*)d_in[0];   // (64, 2048, 512)
    const float* fin    = (const float*)d_in[1];   // (64, 512)
    const float* attn_w = (const float*)d_in[2];   // (512, 1024)
    const float* attn_b = (const float*)d_in[3];   // (512,)
    const float* v_w    = (const float*)d_in[4];   // (1, 512)
    float* out = (float*)d_out;                    // (64, 512)

    cudaFuncSetAttribute(scores_fp16,
                         cudaFuncAttributeMaxDynamicSharedMemorySize, SMEM_BYTES);

    conv_enc_kernel<<<(size_t)BB * SS * HH / 4 / 256, 256>>>(enc);
    conv_w_kernel<<<KK, 256>>>(attn_w);
    cvec_kernel<<<BB, 256>>>(fin, attn_w, attn_b);
    scores_fp16<<<dim3(SS / 128, BB), 256, SMEM_BYTES>>>(v_w);
    softmax_kernel<<<BB, 256>>>();
    context_kernel<<<dim3(16, BB), 128>>>();
    reduce_ctx<<<BB, 512>>>(out);
}